// round 13
// baseline (speedup 1.0000x reference)
#include <cuda_runtime.h>
#include <cuda_fp16.h>
#include <cstdint>
#include <math.h>

#define NB 8
#define NC 256
#define NL 2048
#define BM 128
#define BN 256
#define BK 64                      // halves per chunk (128 bytes per row)
#define NTHREADS 256
#define L2E 1.4426950408889634f

// stage: A 128 rows x 128B (16KB) + B 256 rows x 128B (32KB) = 48KB
#define ABYTES (128 * 128)
#define STB (48 * 1024)
#define SMEM_BYTES (4 * STB)       // 196608 (max over kernels)

// ---------------- scratch ----------------
__device__ __half g_xh[NL * NL];          // fp16 x
__device__ __half g_Wh[3 * NL * NL];      // fp16 Wq|Wk|Wv
__device__ __half g_Qt[NB * NL * NC];     // [b][l][c] scaled
__device__ __half g_Kt[NB * NL * NC];     // [b][m][c]
__device__ __half g_V [NB * NC * NL];     // [b][c][m]
__device__ __half g_S [NB * NL * NL];     // E = exp(score), unnormalized (fp16)
__device__ float  g_part[NB * NL * 8];    // per-(row, m-tile CTA) partial sums

// ---------------- helpers ----------------
__device__ __forceinline__ uint32_t smem_u32(const void* p) {
    uint32_t a;
    asm("{ .reg .u64 t; cvta.to.shared.u64 t, %1; cvt.u32.u64 %0, t; }"
        : "=r"(a) : "l"(p));
    return a;
}
__device__ __forceinline__ float ex2(float x) {
    float r;
    asm("ex2.approx.f32 %0, %1;" : "=f"(r) : "f"(x));
    return r;
}
__device__ __forceinline__ void cp_async16(uint32_t dst, const void* src) {
    asm volatile("cp.async.cg.shared.global [%0], [%1], 16;" :: "r"(dst), "l"(src));
}
__device__ __forceinline__ void ldsm4(uint32_t& r0, uint32_t& r1, uint32_t& r2,
                                      uint32_t& r3, uint32_t addr) {
    asm volatile("ldmatrix.sync.aligned.m8n8.x4.shared.b16 {%0,%1,%2,%3}, [%4];"
                 : "=r"(r0), "=r"(r1), "=r"(r2), "=r"(r3) : "r"(addr));
}
__device__ __forceinline__ void mma_f16(float& d0, float& d1, float& d2, float& d3,
                                        uint32_t a0, uint32_t a1, uint32_t a2, uint32_t a3,
                                        uint32_t b0, uint32_t b1) {
    asm volatile(
        "mma.sync.aligned.m16n8k16.row.col.f32.f16.f16.f32 "
        "{%0,%1,%2,%3}, {%4,%5,%6,%7}, {%8,%9}, {%0,%1,%2,%3};"
        : "+f"(d0), "+f"(d1), "+f"(d2), "+f"(d3)
        : "r"(a0), "r"(a1), "r"(a2), "r"(a3), "r"(b0), "r"(b1));
}

// ===========================================================================
// fp16 mainloop: CTA 128x256, warp 64x64 (2x4 grid), XOR-swizzled smem,
// NSTG-stage cp.async. BK=64 halves per chunk. acc[4][8][4] fp32.
// ===========================================================================
template <int NSTG>
__device__ __forceinline__ void mainloop_h(
    const __half* __restrict__ A, const __half* __restrict__ B,
    int K, int ldA, int ldB, int r0, int c0,
    int tid, int wm, int wn, int lane,
    float acc[4][8][4])
{
    extern __shared__ float smem[];
    const uint32_t sbase = smem_u32(smem);
    const int nch = K / BK;

    const int lrow = tid >> 3;                       // 0..31
    const uint32_t lcb = (uint32_t)((tid & 7) * 16); // byte col within 128B row

    uint32_t qa[4], qb[4];
    {
        const int ar = wm + (lane & 15);
        const uint32_t ac = (uint32_t)(((lane >> 4) & 1) * 16);
#pragma unroll
        for (int mt = 0; mt < 4; mt++) {
            const int r = ar + mt * 16;
            qa[mt] = (uint32_t)(r * 128) + (ac ^ (((uint32_t)r & 7u) << 4));
        }
        const int br = wn + ((lane >> 3) & 1) * 8 + (lane & 7);
        const uint32_t bc = (uint32_t)(((lane >> 4) & 1) * 16);
#pragma unroll
        for (int ntp = 0; ntp < 4; ntp++) {
            const int r = br + ntp * 16;
            qb[ntp] = (uint32_t)(r * 128) + (bc ^ (((uint32_t)r & 7u) << 4));
        }
    }

    auto load_chunk = [&](int i) {
        const int s = i % NSTG;
        const uint32_t dA = sbase + (uint32_t)(s * STB);
        const uint32_t dB = dA + (uint32_t)ABYTES;
        const __half* Ab = A + (size_t)r0 * ldA + (size_t)i * BK + (tid & 7) * 8;
        const __half* Bb = B + (size_t)c0 * ldB + (size_t)i * BK + (tid & 7) * 8;
#pragma unroll
        for (int p = 0; p < 4; p++) {
            const int row = lrow + p * 32;
            const uint32_t off = (uint32_t)(row * 128) + (lcb ^ (((uint32_t)row & 7u) << 4));
            cp_async16(dA + off, Ab + (size_t)row * ldA);
        }
#pragma unroll
        for (int p = 0; p < 8; p++) {
            const int row = lrow + p * 32;
            const uint32_t off = (uint32_t)(row * 128) + (lcb ^ (((uint32_t)row & 7u) << 4));
            cp_async16(dB + off, Bb + (size_t)row * ldB);
        }
        asm volatile("cp.async.commit_group;");
    };

#pragma unroll
    for (int i = 0; i < NSTG - 1; i++) load_chunk(i);
    asm volatile("cp.async.wait_group %0;" :: "n"(NSTG - 2));
    __syncthreads();

    for (int j = 0; j < nch; j++) {
        if (j + NSTG - 1 < nch) load_chunk(j + NSTG - 1);

        const uint32_t sA = sbase + (uint32_t)((j % NSTG) * STB);
        const uint32_t sB = sA + (uint32_t)ABYTES;

#pragma unroll
        for (int s16 = 0; s16 < 4; s16++) {
            const uint32_t kb = (uint32_t)(s16 * 32);
            uint32_t a[4][4], b[4][4];
#pragma unroll
            for (int mt = 0; mt < 4; mt++)
                ldsm4(a[mt][0], a[mt][1], a[mt][2], a[mt][3], (sA + qa[mt]) ^ kb);
#pragma unroll
            for (int ntp = 0; ntp < 4; ntp++)
                ldsm4(b[ntp][0], b[ntp][1], b[ntp][2], b[ntp][3], (sB + qb[ntp]) ^ kb);
#pragma unroll
            for (int mt = 0; mt < 4; mt++)
#pragma unroll
                for (int nt = 0; nt < 8; nt++)
                    mma_f16(acc[mt][nt][0], acc[mt][nt][1], acc[mt][nt][2], acc[mt][nt][3],
                            a[mt][0], a[mt][1], a[mt][2], a[mt][3],
                            b[nt >> 1][nt & 1], b[nt >> 1][(nt & 1) + 2]);
        }

        asm volatile("cp.async.wait_group %0;" :: "n"(NSTG - 2));
        __syncthreads();
    }
}

// ---------------------------------------------------------------------------
// Merged fp32 -> fp16 conversion, 16 floats per thread (MLP 4).
// grid = (NL*NL/16/256, 4)
// ---------------------------------------------------------------------------
__global__ void f2h_all(const float* __restrict__ x,  const float* __restrict__ Wq,
                        const float* __restrict__ Wk, const float* __restrict__ Wv)
{
    const int which = blockIdx.y;
    const float* src = (which == 0) ? x : (which == 1) ? Wq : (which == 2) ? Wk : Wv;
    __half* dst = (which == 0) ? g_xh : g_Wh + (size_t)(which - 1) * NL * NL;

    const int i = blockIdx.x * blockDim.x + threadIdx.x;   // 16 floats each
    float4 a = ((const float4*)src)[4 * i];
    float4 b = ((const float4*)src)[4 * i + 1];
    float4 c = ((const float4*)src)[4 * i + 2];
    float4 d = ((const float4*)src)[4 * i + 3];

    __half2 h0 = __floats2half2_rn(a.x, a.y);
    __half2 h1 = __floats2half2_rn(a.z, a.w);
    __half2 h2 = __floats2half2_rn(b.x, b.y);
    __half2 h3 = __floats2half2_rn(b.z, b.w);
    __half2 h4 = __floats2half2_rn(c.x, c.y);
    __half2 h5 = __floats2half2_rn(c.z, c.w);
    __half2 h6 = __floats2half2_rn(d.x, d.y);
    __half2 h7 = __floats2half2_rn(d.z, d.w);

    uint4 o0, o1;
    o0.x = *(uint32_t*)&h0; o0.y = *(uint32_t*)&h1;
    o0.z = *(uint32_t*)&h2; o0.w = *(uint32_t*)&h3;
    o1.x = *(uint32_t*)&h4; o1.y = *(uint32_t*)&h5;
    o1.z = *(uint32_t*)&h6; o1.w = *(uint32_t*)&h7;
    ((uint4*)dst)[2 * i]     = o0;
    ((uint4*)dst)[2 * i + 1] = o1;
}

// ---------------------------------------------------------------------------
// Merged QKV projection GEMM. cols 0..2047 -> Q (transposed+scaled),
// 2048..4095 -> K (transposed), 4096..6143 -> V (plain).
// ---------------------------------------------------------------------------
__global__ __launch_bounds__(NTHREADS)
void qkv_gemm(const float* __restrict__ bq, const float* __restrict__ bk,
              const float* __restrict__ bv)
{
    const int tid = threadIdx.x;
    const int wid = tid >> 5;
    const int lane = tid & 31;
    const int g = lane >> 2;
    const int t = lane & 3;
    const int wm = (wid & 1) * 64;
    const int wn = (wid >> 1) * 64;

    const int r0 = blockIdx.y * BM;
    const int gc0 = blockIdx.x * BN;
    const int widx = gc0 >> 11;
    const int c0 = gc0 & (NL - 1);

    const __half* W   = g_Wh + (size_t)widx * NL * NL;
    const float* bias = (widx == 0) ? bq : (widx == 1) ? bk : bv;
    const float scale = (widx == 0) ? 0.022097086912079612f : 1.0f;

    float acc[4][8][4];
#pragma unroll
    for (int i = 0; i < 4; i++)
#pragma unroll
        for (int j = 0; j < 8; j++)
#pragma unroll
            for (int k = 0; k < 4; k++) acc[i][j][k] = 0.0f;

    mainloop_h<4>(g_xh, W, NL, NL, NL, r0, c0, tid, wm, wn, lane, acc);

    const int bb  = r0 >> 8;
    const int cl0 = r0 & (NC - 1);

    if (widx < 2) {
        __half* Tb = ((widx == 0) ? g_Qt : g_Kt) + (size_t)bb * NL * NC;
#pragma unroll
        for (int mt = 0; mt < 4; mt++) {
            const int cA = cl0 + wm + mt * 16 + g;
#pragma unroll
            for (int nt = 0; nt < 8; nt++) {
                const int l0 = c0 + wn + nt * 8 + 2 * t;
                const float b0 = bias[l0], b1 = bias[l0 + 1];
                Tb[(size_t)l0 * NC + cA]           = __float2half_rn((acc[mt][nt][0] + b0) * scale);
                Tb[(size_t)(l0 + 1) * NC + cA]     = __float2half_rn((acc[mt][nt][1] + b1) * scale);
                Tb[(size_t)l0 * NC + cA + 8]       = __float2half_rn((acc[mt][nt][2] + b0) * scale);
                Tb[(size_t)(l0 + 1) * NC + cA + 8] = __float2half_rn((acc[mt][nt][3] + b1) * scale);
            }
        }
    } else {
#pragma unroll
        for (int mt = 0; mt < 4; mt++) {
            const int row = r0 + wm + mt * 16 + g;
#pragma unroll
            for (int nt = 0; nt < 8; nt++) {
                const int col = c0 + wn + nt * 8 + 2 * t;
                const float b0 = bias[col], b1 = bias[col + 1];
                __half2 lo = __floats2half2_rn(acc[mt][nt][0] + b0, acc[mt][nt][1] + b1);
                __half2 hi = __floats2half2_rn(acc[mt][nt][2] + b0, acc[mt][nt][3] + b1);
                *(__half2*)&g_V[(size_t)row * NL + col]       = lo;
                *(__half2*)&g_V[(size_t)(row + 8) * NL + col] = hi;
            }
        }
    }
}

// ---------------------------------------------------------------------------
// Score GEMM: E[b][l][m] = exp(Qt[b][l][:] . Kt[b][m][:])  (K=256, fp16 E)
// + per-CTA partial row sums -> g_part. NSTG=3 (short K: 4 chunks).
// ---------------------------------------------------------------------------
__global__ __launch_bounds__(NTHREADS)
void score_gemm()
{
    extern __shared__ float smem[];

    const int tid = threadIdx.x;
    const int wid = tid >> 5;
    const int lane = tid & 31;
    const int g = lane >> 2;
    const int t = lane & 3;
    const int wm = (wid & 1) * 64;
    const int wn = (wid >> 1) * 64;
    const int wcol = wid >> 1;        // 0..3

    const int z = blockIdx.z;
    const __half* A = g_Qt + (size_t)z * NL * NC;
    const __half* B = g_Kt + (size_t)z * NL * NC;
    const int r0 = blockIdx.y * BM;
    const int c0 = blockIdx.x * BN;

    float acc[4][8][4];
#pragma unroll
    for (int i = 0; i < 4; i++)
#pragma unroll
        for (int j = 0; j < 8; j++)
#pragma unroll
            for (int k = 0; k < 4; k++) acc[i][j][k] = 0.0f;

    mainloop_h<3>(A, B, NC, NC, NC, r0, c0, tid, wm, wn, lane, acc);

    __half* Cb = g_S + (size_t)z * NL * NL;
    float rsum[4][2];
#pragma unroll
    for (int mt = 0; mt < 4; mt++) { rsum[mt][0] = 0.0f; rsum[mt][1] = 0.0f; }

#pragma unroll
    for (int mt = 0; mt < 4; mt++) {
        const int row = r0 + wm + mt * 16 + g;
#pragma unroll
        for (int nt = 0; nt < 8; nt++) {
            const int col = c0 + wn + nt * 8 + 2 * t;
            float e0 = ex2(acc[mt][nt][0] * L2E);
            float e1 = ex2(acc[mt][nt][1] * L2E);
            float e2 = ex2(acc[mt][nt][2] * L2E);
            float e3 = ex2(acc[mt][nt][3] * L2E);
            rsum[mt][0] += e0 + e1;
            rsum[mt][1] += e2 + e3;
            *(__half2*)&Cb[(size_t)row * NL + col]       = __floats2half2_rn(e0, e1);
            *(__half2*)&Cb[(size_t)(row + 8) * NL + col] = __floats2half2_rn(e2, e3);
        }
    }

#pragma unroll
    for (int mt = 0; mt < 4; mt++)
#pragma unroll
        for (int h = 0; h < 2; h++) {
            rsum[mt][h] += __shfl_xor_sync(0xFFFFFFFFu, rsum[mt][h], 1);
            rsum[mt][h] += __shfl_xor_sync(0xFFFFFFFFu, rsum[mt][h], 2);
        }

    float* sred = smem;
    if (t == 0) {
#pragma unroll
        for (int mt = 0; mt < 4; mt++) {
            const int rl = wm + mt * 16 + g;
            sred[rl * 4 + wcol]       = rsum[mt][0];
            sred[(rl + 8) * 4 + wcol] = rsum[mt][1];
        }
    }
    __syncthreads();
    if (tid < 128) {
        const float s4 = sred[tid * 4 + 0] + sred[tid * 4 + 1]
                       + sred[tid * 4 + 2] + sred[tid * 4 + 3];
        g_part[((size_t)z * NL + r0 + tid) * 8 + blockIdx.x] = s4;
    }
}

// ---------------------------------------------------------------------------
// Output GEMM: out[b][c][l] = (V[b][c][:] . E[b][l][:]) / rowsum(E)[l]
// Inverse row sums computed inline from g_part (L2-hot).
// ---------------------------------------------------------------------------
__global__ __launch_bounds__(NTHREADS)
void out_gemm(float* __restrict__ out)
{
    const int tid = threadIdx.x;
    const int wid = tid >> 5;
    const int lane = tid & 31;
    const int g = lane >> 2;
    const int t = lane & 3;
    const int wm = (wid & 1) * 64;
    const int wn = (wid >> 1) * 64;

    const int z = blockIdx.z;
    const __half* A = g_V + (size_t)z * NC * NL;
    const __half* B = g_S + (size_t)z * NL * NL;
    const int r0 = blockIdx.y * BM;
    const int c0 = blockIdx.x * BN;

    float acc[4][8][4];
#pragma unroll
    for (int i = 0; i < 4; i++)
#pragma unroll
        for (int j = 0; j < 8; j++)
#pragma unroll
            for (int k = 0; k < 4; k++) acc[i][j][k] = 0.0f;

    mainloop_h<4>(A, B, NL, NL, NL, r0, c0, tid, wm, wn, lane, acc);

    // inline inverse row sums from partials (same add order as old inv_kernel)
    const float* pb = g_part + (size_t)z * NL * 8;
    float iv[8][2];
#pragma unroll
    for (int nt = 0; nt < 8; nt++) {
        const int col = c0 + wn + nt * 8 + 2 * t;
#pragma unroll
        for (int h = 0; h < 2; h++) {
            float4 a4 = *(const float4*)&pb[(size_t)(col + h) * 8];
            float4 b4 = *(const float4*)&pb[(size_t)(col + h) * 8 + 4];
            const float tot = (a4.x + a4.y) + (a4.z + a4.w)
                            + (b4.x + b4.y) + (b4.z + b4.w);
            iv[nt][h] = 1.0f / tot;
        }
    }

    float* Cb = out + (size_t)z * NC * NL;
#pragma unroll
    for (int mt = 0; mt < 4; mt++) {
        const int row = r0 + wm + mt * 16 + g;
#pragma unroll
        for (int nt = 0; nt < 8; nt++) {
            const int col = c0 + wn + nt * 8 + 2 * t;
            *(float2*)&Cb[(size_t)row * NL + col] =
                make_float2(acc[mt][nt][0] * iv[nt][0], acc[mt][nt][1] * iv[nt][1]);
            *(float2*)&Cb[(size_t)(row + 8) * NL + col] =
                make_float2(acc[mt][nt][2] * iv[nt][0], acc[mt][nt][3] * iv[nt][1]);
        }
    }
}

// ---------------------------------------------------------------------------
extern "C" void kernel_launch(void* const* d_in, const int* in_sizes, int n_in,
                              void* d_out, int out_size)
{
    const float* x  = (const float*)d_in[0];
    const float* Wq = (const float*)d_in[1];
    const float* bq = (const float*)d_in[2];
    const float* Wk = (const float*)d_in[3];
    const float* bk = (const float*)d_in[4];
    const float* Wv = (const float*)d_in[5];
    const float* bv = (const float*)d_in[6];
    float* out = (float*)d_out;

    cudaFuncSetAttribute((const void*)qkv_gemm,   cudaFuncAttributeMaxDynamicSharedMemorySize, SMEM_BYTES);
    cudaFuncSetAttribute((const void*)score_gemm, cudaFuncAttributeMaxDynamicSharedMemorySize, SMEM_BYTES);
    cudaFuncSetAttribute((const void*)out_gemm,   cudaFuncAttributeMaxDynamicSharedMemorySize, SMEM_BYTES);

    // 0) fp32 -> fp16 conversion (one launch, 16 floats/thread)
    f2h_all<<<dim3(NL * NL / 16 / 256, 4), 256>>>(x, Wq, Wk, Wv);

    // 1) fused QKV projections (N = 6144)
    qkv_gemm<<<dim3(3 * NL / BN, (NB * NC) / BM, 1), NTHREADS, SMEM_BYTES>>>(bq, bk, bv);

    // 2) E = exp(scaled scores) + per-CTA row partial sums (K = 256)
    score_gemm<<<dim3(NL / BN, NL / BM, NB), NTHREADS, SMEM_BYTES>>>();

    // 3) out[b][c][l] = (V . E) * inv[l]  (K = 2048, inv inline)
    out_gemm<<<dim3(NL / BN, NC / BM, NB), NTHREADS, SMEM_BYTES>>>(out);
}

// round 14
// speedup vs baseline: 1.0094x; 1.0094x over previous
#include <cuda_runtime.h>
#include <cuda_fp16.h>
#include <cstdint>
#include <math.h>

#define NB 8
#define NC 256
#define NL 2048
#define BM 128
#define BN 256
#define BK 64                      // halves per chunk (128 bytes per row)
#define NTHREADS 256
#define NST 4
#define L2E 1.4426950408889634f

// stage: A 128 rows x 128B (16KB) + B 256 rows x 128B (32KB) = 48KB
#define ABYTES (128 * 128)
#define STB (48 * 1024)
#define SMEM_BYTES (NST * STB)     // 196608

// ---------------- scratch ----------------
__device__ __half g_xh[NL * NL];          // fp16 x
__device__ __half g_Wh[3 * NL * NL];      // fp16 Wq|Wk|Wv
__device__ __half g_Qt[NB * NL * NC];     // [b][l][c] scaled
__device__ __half g_Kt[NB * NL * NC];     // [b][m][c]
__device__ __half g_V [NB * NC * NL];     // [b][c][m]
__device__ __half g_S [NB * NL * NL];     // E = exp(score), unnormalized (fp16)
__device__ float  g_part[NB * NL * 8];    // per-(row, m-tile CTA) partial sums
__device__ float  g_inv[NB * NL];         // 1 / row sum of E

// ---------------- helpers ----------------
__device__ __forceinline__ uint32_t smem_u32(const void* p) {
    uint32_t a;
    asm("{ .reg .u64 t; cvta.to.shared.u64 t, %1; cvt.u32.u64 %0, t; }"
        : "=r"(a) : "l"(p));
    return a;
}
__device__ __forceinline__ float ex2(float x) {
    float r;
    asm("ex2.approx.f32 %0, %1;" : "=f"(r) : "f"(x));
    return r;
}
__device__ __forceinline__ void cp_async16(uint32_t dst, const void* src) {
    asm volatile("cp.async.cg.shared.global [%0], [%1], 16;" :: "r"(dst), "l"(src));
}
__device__ __forceinline__ void ldsm4(uint32_t& r0, uint32_t& r1, uint32_t& r2,
                                      uint32_t& r3, uint32_t addr) {
    asm volatile("ldmatrix.sync.aligned.m8n8.x4.shared.b16 {%0,%1,%2,%3}, [%4];"
                 : "=r"(r0), "=r"(r1), "=r"(r2), "=r"(r3) : "r"(addr));
}
__device__ __forceinline__ void mma_f16(float& d0, float& d1, float& d2, float& d3,
                                        uint32_t a0, uint32_t a1, uint32_t a2, uint32_t a3,
                                        uint32_t b0, uint32_t b1) {
    asm volatile(
        "mma.sync.aligned.m16n8k16.row.col.f32.f16.f16.f32 "
        "{%0,%1,%2,%3}, {%4,%5,%6,%7}, {%8,%9}, {%0,%1,%2,%3};"
        : "+f"(d0), "+f"(d1), "+f"(d2), "+f"(d3)
        : "r"(a0), "r"(a1), "r"(a2), "r"(a3), "r"(b0), "r"(b1));
}

// ===========================================================================
// fp16 mainloop: CTA 128x256, warp 64x64 (2x4 grid), XOR-swizzled smem,
// NST-stage cp.async. BK=64 halves per chunk. acc[4][8][4] fp32.
// ===========================================================================
__device__ __forceinline__ void mainloop_h(
    const __half* __restrict__ A, const __half* __restrict__ B,
    int K, int ldA, int ldB, int r0, int c0,
    int tid, int wm, int wn, int lane,
    float acc[4][8][4])
{
    extern __shared__ float smem[];
    const uint32_t sbase = smem_u32(smem);
    const int nch = K / BK;

    const int lrow = tid >> 3;                       // 0..31
    const uint32_t lcb = (uint32_t)((tid & 7) * 16); // byte col within 128B row

    uint32_t qa[4], qb[4];
    {
        const int ar = wm + (lane & 15);
        const uint32_t ac = (uint32_t)(((lane >> 4) & 1) * 16);
#pragma unroll
        for (int mt = 0; mt < 4; mt++) {
            const int r = ar + mt * 16;
            qa[mt] = (uint32_t)(r * 128) + (ac ^ (((uint32_t)r & 7u) << 4));
        }
        const int br = wn + ((lane >> 3) & 1) * 8 + (lane & 7);
        const uint32_t bc = (uint32_t)(((lane >> 4) & 1) * 16);
#pragma unroll
        for (int ntp = 0; ntp < 4; ntp++) {
            const int r = br + ntp * 16;
            qb[ntp] = (uint32_t)(r * 128) + (bc ^ (((uint32_t)r & 7u) << 4));
        }
    }

    auto load_chunk = [&](int i) {
        const int s = i % NST;
        const uint32_t dA = sbase + (uint32_t)(s * STB);
        const uint32_t dB = dA + (uint32_t)ABYTES;
        const __half* Ab = A + (size_t)r0 * ldA + (size_t)i * BK + (tid & 7) * 8;
        const __half* Bb = B + (size_t)c0 * ldB + (size_t)i * BK + (tid & 7) * 8;
#pragma unroll
        for (int p = 0; p < 4; p++) {
            const int row = lrow + p * 32;
            const uint32_t off = (uint32_t)(row * 128) + (lcb ^ (((uint32_t)row & 7u) << 4));
            cp_async16(dA + off, Ab + (size_t)row * ldA);
        }
#pragma unroll
        for (int p = 0; p < 8; p++) {
            const int row = lrow + p * 32;
            const uint32_t off = (uint32_t)(row * 128) + (lcb ^ (((uint32_t)row & 7u) << 4));
            cp_async16(dB + off, Bb + (size_t)row * ldB);
        }
        asm volatile("cp.async.commit_group;");
    };

#pragma unroll
    for (int i = 0; i < NST - 1; i++) load_chunk(i);
    asm volatile("cp.async.wait_group %0;" :: "n"(NST - 2));
    __syncthreads();

    for (int j = 0; j < nch; j++) {
        if (j + NST - 1 < nch) load_chunk(j + NST - 1);

        const uint32_t sA = sbase + (uint32_t)((j % NST) * STB);
        const uint32_t sB = sA + (uint32_t)ABYTES;

#pragma unroll
        for (int s16 = 0; s16 < 4; s16++) {
            const uint32_t kb = (uint32_t)(s16 * 32);
            uint32_t a[4][4], b[4][4];
#pragma unroll
            for (int mt = 0; mt < 4; mt++)
                ldsm4(a[mt][0], a[mt][1], a[mt][2], a[mt][3], (sA + qa[mt]) ^ kb);
#pragma unroll
            for (int ntp = 0; ntp < 4; ntp++)
                ldsm4(b[ntp][0], b[ntp][1], b[ntp][2], b[ntp][3], (sB + qb[ntp]) ^ kb);
#pragma unroll
            for (int mt = 0; mt < 4; mt++)
#pragma unroll
                for (int nt = 0; nt < 8; nt++)
                    mma_f16(acc[mt][nt][0], acc[mt][nt][1], acc[mt][nt][2], acc[mt][nt][3],
                            a[mt][0], a[mt][1], a[mt][2], a[mt][3],
                            b[nt >> 1][nt & 1], b[nt >> 1][(nt & 1) + 2]);
        }

        asm volatile("cp.async.wait_group %0;" :: "n"(NST - 2));
        __syncthreads();
    }
}

// ---------------------------------------------------------------------------
// Merged fp32 -> fp16 conversion, 16 floats per thread (MLP 4).
// grid = (NL*NL/16/256, 4)
// ---------------------------------------------------------------------------
__global__ void f2h_all(const float* __restrict__ x,  const float* __restrict__ Wq,
                        const float* __restrict__ Wk, const float* __restrict__ Wv)
{
    const int which = blockIdx.y;
    const float* src = (which == 0) ? x : (which == 1) ? Wq : (which == 2) ? Wk : Wv;
    __half* dst = (which == 0) ? g_xh : g_Wh + (size_t)(which - 1) * NL * NL;

    const int i = blockIdx.x * blockDim.x + threadIdx.x;   // 16 floats each
    float4 a = ((const float4*)src)[4 * i];
    float4 b = ((const float4*)src)[4 * i + 1];
    float4 c = ((const float4*)src)[4 * i + 2];
    float4 d = ((const float4*)src)[4 * i + 3];

    __half2 h0 = __floats2half2_rn(a.x, a.y);
    __half2 h1 = __floats2half2_rn(a.z, a.w);
    __half2 h2 = __floats2half2_rn(b.x, b.y);
    __half2 h3 = __floats2half2_rn(b.z, b.w);
    __half2 h4 = __floats2half2_rn(c.x, c.y);
    __half2 h5 = __floats2half2_rn(c.z, c.w);
    __half2 h6 = __floats2half2_rn(d.x, d.y);
    __half2 h7 = __floats2half2_rn(d.z, d.w);

    uint4 o0, o1;
    o0.x = *(uint32_t*)&h0; o0.y = *(uint32_t*)&h1;
    o0.z = *(uint32_t*)&h2; o0.w = *(uint32_t*)&h3;
    o1.x = *(uint32_t*)&h4; o1.y = *(uint32_t*)&h5;
    o1.z = *(uint32_t*)&h6; o1.w = *(uint32_t*)&h7;
    ((uint4*)dst)[2 * i]     = o0;
    ((uint4*)dst)[2 * i + 1] = o1;
}

// ---------------------------------------------------------------------------
// Merged QKV projection GEMM. cols 0..2047 -> Q (transposed+scaled),
// 2048..4095 -> K (transposed), 4096..6143 -> V (plain).
// ---------------------------------------------------------------------------
__global__ __launch_bounds__(NTHREADS)
void qkv_gemm(const float* __restrict__ bq, const float* __restrict__ bk,
              const float* __restrict__ bv)
{
    const int tid = threadIdx.x;
    const int wid = tid >> 5;
    const int lane = tid & 31;
    const int g = lane >> 2;
    const int t = lane & 3;
    const int wm = (wid & 1) * 64;
    const int wn = (wid >> 1) * 64;

    const int r0 = blockIdx.y * BM;
    const int gc0 = blockIdx.x * BN;
    const int widx = gc0 >> 11;
    const int c0 = gc0 & (NL - 1);

    const __half* W   = g_Wh + (size_t)widx * NL * NL;
    const float* bias = (widx == 0) ? bq : (widx == 1) ? bk : bv;
    const float scale = (widx == 0) ? 0.022097086912079612f : 1.0f;

    float acc[4][8][4];
#pragma unroll
    for (int i = 0; i < 4; i++)
#pragma unroll
        for (int j = 0; j < 8; j++)
#pragma unroll
            for (int k = 0; k < 4; k++) acc[i][j][k] = 0.0f;

    mainloop_h(g_xh, W, NL, NL, NL, r0, c0, tid, wm, wn, lane, acc);

    const int bb  = r0 >> 8;
    const int cl0 = r0 & (NC - 1);

    if (widx < 2) {
        __half* Tb = ((widx == 0) ? g_Qt : g_Kt) + (size_t)bb * NL * NC;
#pragma unroll
        for (int mt = 0; mt < 4; mt++) {
            const int cA = cl0 + wm + mt * 16 + g;
#pragma unroll
            for (int nt = 0; nt < 8; nt++) {
                const int l0 = c0 + wn + nt * 8 + 2 * t;
                const float b0 = bias[l0], b1 = bias[l0 + 1];
                Tb[(size_t)l0 * NC + cA]           = __float2half_rn((acc[mt][nt][0] + b0) * scale);
                Tb[(size_t)(l0 + 1) * NC + cA]     = __float2half_rn((acc[mt][nt][1] + b1) * scale);
                Tb[(size_t)l0 * NC + cA + 8]       = __float2half_rn((acc[mt][nt][2] + b0) * scale);
                Tb[(size_t)(l0 + 1) * NC + cA + 8] = __float2half_rn((acc[mt][nt][3] + b1) * scale);
            }
        }
    } else {
#pragma unroll
        for (int mt = 0; mt < 4; mt++) {
            const int row = r0 + wm + mt * 16 + g;
#pragma unroll
            for (int nt = 0; nt < 8; nt++) {
                const int col = c0 + wn + nt * 8 + 2 * t;
                const float b0 = bias[col], b1 = bias[col + 1];
                __half2 lo = __floats2half2_rn(acc[mt][nt][0] + b0, acc[mt][nt][1] + b1);
                __half2 hi = __floats2half2_rn(acc[mt][nt][2] + b0, acc[mt][nt][3] + b1);
                *(__half2*)&g_V[(size_t)row * NL + col]       = lo;
                *(__half2*)&g_V[(size_t)(row + 8) * NL + col] = hi;
            }
        }
    }
}

// ---------------------------------------------------------------------------
// Score GEMM: E[b][l][m] = exp(Qt[b][l][:] . Kt[b][m][:])  (K=256, fp16 E)
// Epilogue also emits per-CTA partial row sums of E (fp32) to g_part.
// ---------------------------------------------------------------------------
__global__ __launch_bounds__(NTHREADS)
void score_gemm()
{
    extern __shared__ float smem[];

    const int tid = threadIdx.x;
    const int wid = tid >> 5;
    const int lane = tid & 31;
    const int g = lane >> 2;
    const int t = lane & 3;
    const int wm = (wid & 1) * 64;
    const int wn = (wid >> 1) * 64;
    const int wcol = wid >> 1;        // 0..3 (warp column index)

    const int z = blockIdx.z;
    const __half* A = g_Qt + (size_t)z * NL * NC;
    const __half* B = g_Kt + (size_t)z * NL * NC;
    const int r0 = blockIdx.y * BM;
    const int c0 = blockIdx.x * BN;

    float acc[4][8][4];
#pragma unroll
    for (int i = 0; i < 4; i++)
#pragma unroll
        for (int j = 0; j < 8; j++)
#pragma unroll
            for (int k = 0; k < 4; k++) acc[i][j][k] = 0.0f;

    mainloop_h(A, B, NC, NC, NC, r0, c0, tid, wm, wn, lane, acc);

    __half* Cb = g_S + (size_t)z * NL * NL;
    float rsum[4][2];                 // per mt: row, row+8 partial col-sums
#pragma unroll
    for (int mt = 0; mt < 4; mt++) { rsum[mt][0] = 0.0f; rsum[mt][1] = 0.0f; }

#pragma unroll
    for (int mt = 0; mt < 4; mt++) {
        const int row = r0 + wm + mt * 16 + g;
#pragma unroll
        for (int nt = 0; nt < 8; nt++) {
            const int col = c0 + wn + nt * 8 + 2 * t;
            float e0 = ex2(acc[mt][nt][0] * L2E);
            float e1 = ex2(acc[mt][nt][1] * L2E);
            float e2 = ex2(acc[mt][nt][2] * L2E);
            float e3 = ex2(acc[mt][nt][3] * L2E);
            rsum[mt][0] += e0 + e1;
            rsum[mt][1] += e2 + e3;
            *(__half2*)&Cb[(size_t)row * NL + col]       = __floats2half2_rn(e0, e1);
            *(__half2*)&Cb[(size_t)(row + 8) * NL + col] = __floats2half2_rn(e2, e3);
        }
    }

    // reduce over t within each quad (lanes 4g+t): xor 1, xor 2
#pragma unroll
    for (int mt = 0; mt < 4; mt++)
#pragma unroll
        for (int h = 0; h < 2; h++) {
            rsum[mt][h] += __shfl_xor_sync(0xFFFFFFFFu, rsum[mt][h], 1);
            rsum[mt][h] += __shfl_xor_sync(0xFFFFFFFFu, rsum[mt][h], 2);
        }

    // cross-warp-column combine via smem [128 rows][4 warp cols]
    float* sred = smem;               // mainloop done; smem free after its last sync
    if (t == 0) {
#pragma unroll
        for (int mt = 0; mt < 4; mt++) {
            const int rl = wm + mt * 16 + g;
            sred[rl * 4 + wcol]       = rsum[mt][0];
            sred[(rl + 8) * 4 + wcol] = rsum[mt][1];
        }
    }
    __syncthreads();
    if (tid < 128) {
        const float s4 = sred[tid * 4 + 0] + sred[tid * 4 + 1]
                       + sred[tid * 4 + 2] + sred[tid * 4 + 3];
        g_part[((size_t)z * NL + r0 + tid) * 8 + blockIdx.x] = s4;
    }
}

// ---------------------------------------------------------------------------
// Combine 8 partials per row -> 1/sum.
// ---------------------------------------------------------------------------
__global__ void inv_kernel()
{
    const int row = blockIdx.x * blockDim.x + threadIdx.x;   // 0 .. NB*NL-1
    float4 a = *(const float4*)&g_part[(size_t)row * 8];
    float4 b = *(const float4*)&g_part[(size_t)row * 8 + 4];
    const float tot = (a.x + a.y) + (a.z + a.w) + (b.x + b.y) + (b.z + b.w);
    g_inv[row] = 1.0f / tot;
}

// ---------------------------------------------------------------------------
// Output GEMM: out[b][c][l] = (V[b][c][:] . E[b][l][:]) * g_inv[b*NL + l]
// ---------------------------------------------------------------------------
__global__ __launch_bounds__(NTHREADS)
void out_gemm(float* __restrict__ out)
{
    const int tid = threadIdx.x;
    const int wid = tid >> 5;
    const int lane = tid & 31;
    const int g = lane >> 2;
    const int t = lane & 3;
    const int wm = (wid & 1) * 64;
    const int wn = (wid >> 1) * 64;

    const int z = blockIdx.z;
    const __half* A = g_V + (size_t)z * NC * NL;
    const __half* B = g_S + (size_t)z * NL * NL;
    const int r0 = blockIdx.y * BM;
    const int c0 = blockIdx.x * BN;

    float acc[4][8][4];
#pragma unroll
    for (int i = 0; i < 4; i++)
#pragma unroll
        for (int j = 0; j < 8; j++)
#pragma unroll
            for (int k = 0; k < 4; k++) acc[i][j][k] = 0.0f;

    mainloop_h(A, B, NL, NL, NL, r0, c0, tid, wm, wn, lane, acc);

    const float* invb = g_inv + (size_t)z * NL;
    float iv[8][2];
#pragma unroll
    for (int nt = 0; nt < 8; nt++) {
        const int col = c0 + wn + nt * 8 + 2 * t;
        iv[nt][0] = invb[col];
        iv[nt][1] = invb[col + 1];
    }

    float* Cb = out + (size_t)z * NC * NL;
#pragma unroll
    for (int mt = 0; mt < 4; mt++) {
        const int row = r0 + wm + mt * 16 + g;
#pragma unroll
        for (int nt = 0; nt < 8; nt++) {
            const int col = c0 + wn + nt * 8 + 2 * t;
            *(float2*)&Cb[(size_t)row * NL + col] =
                make_float2(acc[mt][nt][0] * iv[nt][0], acc[mt][nt][1] * iv[nt][1]);
            *(float2*)&Cb[(size_t)(row + 8) * NL + col] =
                make_float2(acc[mt][nt][2] * iv[nt][0], acc[mt][nt][3] * iv[nt][1]);
        }
    }
}

// ---------------------------------------------------------------------------
extern "C" void kernel_launch(void* const* d_in, const int* in_sizes, int n_in,
                              void* d_out, int out_size)
{
    const float* x  = (const float*)d_in[0];
    const float* Wq = (const float*)d_in[1];
    const float* bq = (const float*)d_in[2];
    const float* Wk = (const float*)d_in[3];
    const float* bk = (const float*)d_in[4];
    const float* Wv = (const float*)d_in[5];
    const float* bv = (const float*)d_in[6];
    float* out = (float*)d_out;

    cudaFuncSetAttribute((const void*)qkv_gemm,   cudaFuncAttributeMaxDynamicSharedMemorySize, SMEM_BYTES);
    cudaFuncSetAttribute((const void*)score_gemm, cudaFuncAttributeMaxDynamicSharedMemorySize, SMEM_BYTES);
    cudaFuncSetAttribute((const void*)out_gemm,   cudaFuncAttributeMaxDynamicSharedMemorySize, SMEM_BYTES);

    // 0) fp32 -> fp16 conversion (one launch, 16 floats/thread)
    f2h_all<<<dim3(NL * NL / 16 / 256, 4), 256>>>(x, Wq, Wk, Wv);

    // 1) fused QKV projections (N = 6144)
    qkv_gemm<<<dim3(3 * NL / BN, (NB * NC) / BM, 1), NTHREADS, SMEM_BYTES>>>(bq, bk, bv);

    // 2) E = exp(scaled scores), fp16 + per-CTA row partial sums (K = 256)
    score_gemm<<<dim3(NL / BN, NL / BM, NB), NTHREADS, SMEM_BYTES>>>();

    // 3) combine partials -> 1/rowsum
    inv_kernel<<<NB * NL / 256, 256>>>();

    // 4) out[b][c][l] = (V . E) * inv[l]  (K = 2048)
    out_gemm<<<dim3(NL / BN, NC / BM, NB), NTHREADS, SMEM_BYTES>>>(out);
}

// round 15
// speedup vs baseline: 1.1379x; 1.1273x over previous
#include <cuda_runtime.h>
#include <cuda_fp16.h>
#include <cstdint>
#include <math.h>

#define NB 8
#define NC 256
#define NL 2048
#define BM 128
#define BN 256
#define BK 64                      // halves per chunk (128 bytes per row)
#define NTHREADS 256
#define NST 4
#define L2E 1.4426950408889634f

// stage: A 128 rows x 128B (16KB) + B 256 rows x 128B (32KB) = 48KB
#define ABYTES (128 * 128)
#define STB (48 * 1024)
#define SMEM_BYTES (NST * STB)     // 196608

// ---------------- scratch ----------------
__device__ __half g_xh[NL * NL];          // fp16 x
__device__ __half g_Wh[3 * NL * NL];      // fp16 Wq|Wk|Wv
__device__ __half g_Qt[NB * NL * NC];     // [b][l][c] scaled
__device__ __half g_Kt[NB * NL * NC];     // [b][m][c]
__device__ __half g_V [NB * NC * NL];     // [b][c][m]
__device__ __half g_S [NB * NL * NL];     // E = exp(score), unnormalized (fp16)
__device__ float  g_part[NB * NL * 8];    // per-(row, m-tile CTA) partial sums
__device__ float  g_inv[NB * NL];         // 1 / row sum of E

// ---------------- helpers ----------------
__device__ __forceinline__ uint32_t smem_u32(const void* p) {
    uint32_t a;
    asm("{ .reg .u64 t; cvta.to.shared.u64 t, %1; cvt.u32.u64 %0, t; }"
        : "=r"(a) : "l"(p));
    return a;
}
__device__ __forceinline__ float ex2(float x) {
    float r;
    asm("ex2.approx.f32 %0, %1;" : "=f"(r) : "f"(x));
    return r;
}
__device__ __forceinline__ void cp_async16(uint32_t dst, const void* src) {
    asm volatile("cp.async.cg.shared.global [%0], [%1], 16;" :: "r"(dst), "l"(src));
}
__device__ __forceinline__ void ldsm4(uint32_t& r0, uint32_t& r1, uint32_t& r2,
                                      uint32_t& r3, uint32_t addr) {
    asm volatile("ldmatrix.sync.aligned.m8n8.x4.shared.b16 {%0,%1,%2,%3}, [%4];"
                 : "=r"(r0), "=r"(r1), "=r"(r2), "=r"(r3) : "r"(addr));
}
__device__ __forceinline__ void mma_f16(float& d0, float& d1, float& d2, float& d3,
                                        uint32_t a0, uint32_t a1, uint32_t a2, uint32_t a3,
                                        uint32_t b0, uint32_t b1) {
    asm volatile(
        "mma.sync.aligned.m16n8k16.row.col.f32.f16.f16.f32 "
        "{%0,%1,%2,%3}, {%4,%5,%6,%7}, {%8,%9}, {%0,%1,%2,%3};"
        : "+f"(d0), "+f"(d1), "+f"(d2), "+f"(d3)
        : "r"(a0), "r"(a1), "r"(a2), "r"(a3), "r"(b0), "r"(b1));
}

// ===========================================================================
// fp16 mainloop: CTA 128x256, warp 64x64 (2x4 grid), XOR-swizzled smem,
// NST-stage cp.async, fragment double-buffering (ldsm for k-step s+1 issued
// before MMAs of step s). BK=64 halves per chunk. acc[4][8][4] fp32.
// ===========================================================================
__device__ __forceinline__ void mainloop_h(
    const __half* __restrict__ A, const __half* __restrict__ B,
    int K, int ldA, int ldB, int r0, int c0,
    int tid, int wm, int wn, int lane,
    float acc[4][8][4])
{
    extern __shared__ float smem[];
    const uint32_t sbase = smem_u32(smem);
    const int nch = K / BK;

    const int lrow = tid >> 3;                       // 0..31
    const uint32_t lcb = (uint32_t)((tid & 7) * 16); // byte col within 128B row

    uint32_t qa[4], qb[4];
    {
        const int ar = wm + (lane & 15);
        const uint32_t ac = (uint32_t)(((lane >> 4) & 1) * 16);
#pragma unroll
        for (int mt = 0; mt < 4; mt++) {
            const int r = ar + mt * 16;
            qa[mt] = (uint32_t)(r * 128) + (ac ^ (((uint32_t)r & 7u) << 4));
        }
        const int br = wn + ((lane >> 3) & 1) * 8 + (lane & 7);
        const uint32_t bc = (uint32_t)(((lane >> 4) & 1) * 16);
#pragma unroll
        for (int ntp = 0; ntp < 4; ntp++) {
            const int r = br + ntp * 16;
            qb[ntp] = (uint32_t)(r * 128) + (bc ^ (((uint32_t)r & 7u) << 4));
        }
    }

    auto load_chunk = [&](int i) {
        const int s = i % NST;
        const uint32_t dA = sbase + (uint32_t)(s * STB);
        const uint32_t dB = dA + (uint32_t)ABYTES;
        const __half* Ab = A + (size_t)r0 * ldA + (size_t)i * BK + (tid & 7) * 8;
        const __half* Bb = B + (size_t)c0 * ldB + (size_t)i * BK + (tid & 7) * 8;
#pragma unroll
        for (int p = 0; p < 4; p++) {
            const int row = lrow + p * 32;
            const uint32_t off = (uint32_t)(row * 128) + (lcb ^ (((uint32_t)row & 7u) << 4));
            cp_async16(dA + off, Ab + (size_t)row * ldA);
        }
#pragma unroll
        for (int p = 0; p < 8; p++) {
            const int row = lrow + p * 32;
            const uint32_t off = (uint32_t)(row * 128) + (lcb ^ (((uint32_t)row & 7u) << 4));
            cp_async16(dB + off, Bb + (size_t)row * ldB);
        }
        asm volatile("cp.async.commit_group;");
    };

    // fragment double buffers
    uint32_t a[2][4][4], b[2][4][4];

    auto load_frags = [&](int buf, uint32_t sA, uint32_t sB, int s16) {
        const uint32_t kb = (uint32_t)(s16 * 32);
#pragma unroll
        for (int mt = 0; mt < 4; mt++)
            ldsm4(a[buf][mt][0], a[buf][mt][1], a[buf][mt][2], a[buf][mt][3],
                  (sA + qa[mt]) ^ kb);
#pragma unroll
        for (int ntp = 0; ntp < 4; ntp++)
            ldsm4(b[buf][ntp][0], b[buf][ntp][1], b[buf][ntp][2], b[buf][ntp][3],
                  (sB + qb[ntp]) ^ kb);
    };

    auto mma_all = [&](int buf) {
#pragma unroll
        for (int mt = 0; mt < 4; mt++)
#pragma unroll
            for (int nt = 0; nt < 8; nt++)
                mma_f16(acc[mt][nt][0], acc[mt][nt][1], acc[mt][nt][2], acc[mt][nt][3],
                        a[buf][mt][0], a[buf][mt][1], a[buf][mt][2], a[buf][mt][3],
                        b[buf][nt >> 1][nt & 1], b[buf][nt >> 1][(nt & 1) + 2]);
    };

    // prologue: NST-1 chunks in flight, then first frag load
#pragma unroll
    for (int i = 0; i < NST - 1; i++) load_chunk(i);
    asm volatile("cp.async.wait_group %0;" :: "n"(NST - 2));
    __syncthreads();
    load_frags(0, sbase, sbase + (uint32_t)ABYTES, 0);

    for (int j = 0; j < nch; j++) {
        const uint32_t sA = sbase + (uint32_t)((j % NST) * STB);
        const uint32_t sB = sA + (uint32_t)ABYTES;
        if (j + NST - 1 < nch) load_chunk(j + NST - 1);

#pragma unroll
        for (int s16 = 0; s16 < 4; s16++) {
            const int cur = s16 & 1, nxt = cur ^ 1;
            if (s16 < 3) {
                load_frags(nxt, sA, sB, s16 + 1);
                mma_all(cur);
            } else {
                mma_all(cur);        // consume last frags before barrier
                if (j + 1 < nch) {
                    asm volatile("cp.async.wait_group %0;" :: "n"(NST - 2));
                    __syncthreads();
                    const uint32_t nA = sbase + (uint32_t)(((j + 1) % NST) * STB);
                    load_frags(nxt, nA, nA + (uint32_t)ABYTES, 0);
                }
            }
        }
    }
}

// ---------------------------------------------------------------------------
// Merged fp32 -> fp16 conversion, 16 floats per thread (MLP 4).
// grid = (NL*NL/16/256, 4)
// ---------------------------------------------------------------------------
__global__ void f2h_all(const float* __restrict__ x,  const float* __restrict__ Wq,
                        const float* __restrict__ Wk, const float* __restrict__ Wv)
{
    const int which = blockIdx.y;
    const float* src = (which == 0) ? x : (which == 1) ? Wq : (which == 2) ? Wk : Wv;
    __half* dst = (which == 0) ? g_xh : g_Wh + (size_t)(which - 1) * NL * NL;

    const int i = blockIdx.x * blockDim.x + threadIdx.x;   // 16 floats each
    float4 a = ((const float4*)src)[4 * i];
    float4 b = ((const float4*)src)[4 * i + 1];
    float4 c = ((const float4*)src)[4 * i + 2];
    float4 d = ((const float4*)src)[4 * i + 3];

    __half2 h0 = __floats2half2_rn(a.x, a.y);
    __half2 h1 = __floats2half2_rn(a.z, a.w);
    __half2 h2 = __floats2half2_rn(b.x, b.y);
    __half2 h3 = __floats2half2_rn(b.z, b.w);
    __half2 h4 = __floats2half2_rn(c.x, c.y);
    __half2 h5 = __floats2half2_rn(c.z, c.w);
    __half2 h6 = __floats2half2_rn(d.x, d.y);
    __half2 h7 = __floats2half2_rn(d.z, d.w);

    uint4 o0, o1;
    o0.x = *(uint32_t*)&h0; o0.y = *(uint32_t*)&h1;
    o0.z = *(uint32_t*)&h2; o0.w = *(uint32_t*)&h3;
    o1.x = *(uint32_t*)&h4; o1.y = *(uint32_t*)&h5;
    o1.z = *(uint32_t*)&h6; o1.w = *(uint32_t*)&h7;
    ((uint4*)dst)[2 * i]     = o0;
    ((uint4*)dst)[2 * i + 1] = o1;
}

// ---------------------------------------------------------------------------
// Merged QKV projection GEMM. cols 0..2047 -> Q (transposed+scaled),
// 2048..4095 -> K (transposed), 4096..6143 -> V (plain).
// ---------------------------------------------------------------------------
__global__ __launch_bounds__(NTHREADS)
void qkv_gemm(const float* __restrict__ bq, const float* __restrict__ bk,
              const float* __restrict__ bv)
{
    const int tid = threadIdx.x;
    const int wid = tid >> 5;
    const int lane = tid & 31;
    const int g = lane >> 2;
    const int t = lane & 3;
    const int wm = (wid & 1) * 64;
    const int wn = (wid >> 1) * 64;

    const int r0 = blockIdx.y * BM;
    const int gc0 = blockIdx.x * BN;
    const int widx = gc0 >> 11;
    const int c0 = gc0 & (NL - 1);

    const __half* W   = g_Wh + (size_t)widx * NL * NL;
    const float* bias = (widx == 0) ? bq : (widx == 1) ? bk : bv;
    const float scale = (widx == 0) ? 0.022097086912079612f : 1.0f;

    float acc[4][8][4];
#pragma unroll
    for (int i = 0; i < 4; i++)
#pragma unroll
        for (int j = 0; j < 8; j++)
#pragma unroll
            for (int k = 0; k < 4; k++) acc[i][j][k] = 0.0f;

    mainloop_h(g_xh, W, NL, NL, NL, r0, c0, tid, wm, wn, lane, acc);

    const int bb  = r0 >> 8;
    const int cl0 = r0 & (NC - 1);

    if (widx < 2) {
        __half* Tb = ((widx == 0) ? g_Qt : g_Kt) + (size_t)bb * NL * NC;
#pragma unroll
        for (int mt = 0; mt < 4; mt++) {
            const int cA = cl0 + wm + mt * 16 + g;
#pragma unroll
            for (int nt = 0; nt < 8; nt++) {
                const int l0 = c0 + wn + nt * 8 + 2 * t;
                const float b0 = bias[l0], b1 = bias[l0 + 1];
                Tb[(size_t)l0 * NC + cA]           = __float2half_rn((acc[mt][nt][0] + b0) * scale);
                Tb[(size_t)(l0 + 1) * NC + cA]     = __float2half_rn((acc[mt][nt][1] + b1) * scale);
                Tb[(size_t)l0 * NC + cA + 8]       = __float2half_rn((acc[mt][nt][2] + b0) * scale);
                Tb[(size_t)(l0 + 1) * NC + cA + 8] = __float2half_rn((acc[mt][nt][3] + b1) * scale);
            }
        }
    } else {
#pragma unroll
        for (int mt = 0; mt < 4; mt++) {
            const int row = r0 + wm + mt * 16 + g;
#pragma unroll
            for (int nt = 0; nt < 8; nt++) {
                const int col = c0 + wn + nt * 8 + 2 * t;
                const float b0 = bias[col], b1 = bias[col + 1];
                __half2 lo = __floats2half2_rn(acc[mt][nt][0] + b0, acc[mt][nt][1] + b1);
                __half2 hi = __floats2half2_rn(acc[mt][nt][2] + b0, acc[mt][nt][3] + b1);
                *(__half2*)&g_V[(size_t)row * NL + col]       = lo;
                *(__half2*)&g_V[(size_t)(row + 8) * NL + col] = hi;
            }
        }
    }
}

// ---------------------------------------------------------------------------
// Score GEMM: E[b][l][m] = exp(Qt[b][l][:] . Kt[b][m][:])  (K=256, fp16 E)
// Epilogue also emits per-CTA partial row sums of E (fp32) to g_part.
// ---------------------------------------------------------------------------
__global__ __launch_bounds__(NTHREADS)
void score_gemm()
{
    extern __shared__ float smem[];

    const int tid = threadIdx.x;
    const int wid = tid >> 5;
    const int lane = tid & 31;
    const int g = lane >> 2;
    const int t = lane & 3;
    const int wm = (wid & 1) * 64;
    const int wn = (wid >> 1) * 64;
    const int wcol = wid >> 1;        // 0..3 (warp column index)

    const int z = blockIdx.z;
    const __half* A = g_Qt + (size_t)z * NL * NC;
    const __half* B = g_Kt + (size_t)z * NL * NC;
    const int r0 = blockIdx.y * BM;
    const int c0 = blockIdx.x * BN;

    float acc[4][8][4];
#pragma unroll
    for (int i = 0; i < 4; i++)
#pragma unroll
        for (int j = 0; j < 8; j++)
#pragma unroll
            for (int k = 0; k < 4; k++) acc[i][j][k] = 0.0f;

    mainloop_h(A, B, NC, NC, NC, r0, c0, tid, wm, wn, lane, acc);

    __half* Cb = g_S + (size_t)z * NL * NL;
    float rsum[4][2];                 // per mt: row, row+8 partial col-sums
#pragma unroll
    for (int mt = 0; mt < 4; mt++) { rsum[mt][0] = 0.0f; rsum[mt][1] = 0.0f; }

#pragma unroll
    for (int mt = 0; mt < 4; mt++) {
        const int row = r0 + wm + mt * 16 + g;
#pragma unroll
        for (int nt = 0; nt < 8; nt++) {
            const int col = c0 + wn + nt * 8 + 2 * t;
            float e0 = ex2(acc[mt][nt][0] * L2E);
            float e1 = ex2(acc[mt][nt][1] * L2E);
            float e2 = ex2(acc[mt][nt][2] * L2E);
            float e3 = ex2(acc[mt][nt][3] * L2E);
            rsum[mt][0] += e0 + e1;
            rsum[mt][1] += e2 + e3;
            *(__half2*)&Cb[(size_t)row * NL + col]       = __floats2half2_rn(e0, e1);
            *(__half2*)&Cb[(size_t)(row + 8) * NL + col] = __floats2half2_rn(e2, e3);
        }
    }

    // reduce over t within each quad (lanes 4g+t): xor 1, xor 2
#pragma unroll
    for (int mt = 0; mt < 4; mt++)
#pragma unroll
        for (int h = 0; h < 2; h++) {
            rsum[mt][h] += __shfl_xor_sync(0xFFFFFFFFu, rsum[mt][h], 1);
            rsum[mt][h] += __shfl_xor_sync(0xFFFFFFFFu, rsum[mt][h], 2);
        }

    // cross-warp-column combine via smem [128 rows][4 warp cols]
    float* sred = smem;               // mainloop done; smem free after its last sync
    __syncthreads();
    if (t == 0) {
#pragma unroll
        for (int mt = 0; mt < 4; mt++) {
            const int rl = wm + mt * 16 + g;
            sred[rl * 4 + wcol]       = rsum[mt][0];
            sred[(rl + 8) * 4 + wcol] = rsum[mt][1];
        }
    }
    __syncthreads();
    if (tid < 128) {
        const float s4 = sred[tid * 4 + 0] + sred[tid * 4 + 1]
                       + sred[tid * 4 + 2] + sred[tid * 4 + 3];
        g_part[((size_t)z * NL + r0 + tid) * 8 + blockIdx.x] = s4;
    }
}

// ---------------------------------------------------------------------------
// Combine 8 partials per row -> 1/sum.
// ---------------------------------------------------------------------------
__global__ void inv_kernel()
{
    const int row = blockIdx.x * blockDim.x + threadIdx.x;   // 0 .. NB*NL-1
    float4 a = *(const float4*)&g_part[(size_t)row * 8];
    float4 b = *(const float4*)&g_part[(size_t)row * 8 + 4];
    const float tot = (a.x + a.y) + (a.z + a.w) + (b.x + b.y) + (b.z + b.w);
    g_inv[row] = 1.0f / tot;
}

// ---------------------------------------------------------------------------
// Output GEMM: out[b][c][l] = (V[b][c][:] . E[b][l][:]) * g_inv[b*NL + l]
// ---------------------------------------------------------------------------
__global__ __launch_bounds__(NTHREADS)
void out_gemm(float* __restrict__ out)
{
    const int tid = threadIdx.x;
    const int wid = tid >> 5;
    const int lane = tid & 31;
    const int g = lane >> 2;
    const int t = lane & 3;
    const int wm = (wid & 1) * 64;
    const int wn = (wid >> 1) * 64;

    const int z = blockIdx.z;
    const __half* A = g_V + (size_t)z * NC * NL;
    const __half* B = g_S + (size_t)z * NL * NL;
    const int r0 = blockIdx.y * BM;
    const int c0 = blockIdx.x * BN;

    float acc[4][8][4];
#pragma unroll
    for (int i = 0; i < 4; i++)
#pragma unroll
        for (int j = 0; j < 8; j++)
#pragma unroll
            for (int k = 0; k < 4; k++) acc[i][j][k] = 0.0f;

    mainloop_h(A, B, NL, NL, NL, r0, c0, tid, wm, wn, lane, acc);

    const float* invb = g_inv + (size_t)z * NL;
    float iv[8][2];
#pragma unroll
    for (int nt = 0; nt < 8; nt++) {
        const int col = c0 + wn + nt * 8 + 2 * t;
        iv[nt][0] = invb[col];
        iv[nt][1] = invb[col + 1];
    }

    float* Cb = out + (size_t)z * NC * NL;
#pragma unroll
    for (int mt = 0; mt < 4; mt++) {
        const int row = r0 + wm + mt * 16 + g;
#pragma unroll
        for (int nt = 0; nt < 8; nt++) {
            const int col = c0 + wn + nt * 8 + 2 * t;
            *(float2*)&Cb[(size_t)row * NL + col] =
                make_float2(acc[mt][nt][0] * iv[nt][0], acc[mt][nt][1] * iv[nt][1]);
            *(float2*)&Cb[(size_t)(row + 8) * NL + col] =
                make_float2(acc[mt][nt][2] * iv[nt][0], acc[mt][nt][3] * iv[nt][1]);
        }
    }
}

// ---------------------------------------------------------------------------
extern "C" void kernel_launch(void* const* d_in, const int* in_sizes, int n_in,
                              void* d_out, int out_size)
{
    const float* x  = (const float*)d_in[0];
    const float* Wq = (const float*)d_in[1];
    const float* bq = (const float*)d_in[2];
    const float* Wk = (const float*)d_in[3];
    const float* bk = (const float*)d_in[4];
    const float* Wv = (const float*)d_in[5];
    const float* bv = (const float*)d_in[6];
    float* out = (float*)d_out;

    cudaFuncSetAttribute((const void*)qkv_gemm,   cudaFuncAttributeMaxDynamicSharedMemorySize, SMEM_BYTES);
    cudaFuncSetAttribute((const void*)score_gemm, cudaFuncAttributeMaxDynamicSharedMemorySize, SMEM_BYTES);
    cudaFuncSetAttribute((const void*)out_gemm,   cudaFuncAttributeMaxDynamicSharedMemorySize, SMEM_BYTES);

    // 0) fp32 -> fp16 conversion (one launch, 16 floats/thread)
    f2h_all<<<dim3(NL * NL / 16 / 256, 4), 256>>>(x, Wq, Wk, Wv);

    // 1) fused QKV projections (N = 6144)
    qkv_gemm<<<dim3(3 * NL / BN, (NB * NC) / BM, 1), NTHREADS, SMEM_BYTES>>>(bq, bk, bv);

    // 2) E = exp(scaled scores), fp16 + per-CTA row partial sums (K = 256)
    score_gemm<<<dim3(NL / BN, NL / BM, NB), NTHREADS, SMEM_BYTES>>>();

    // 3) combine partials -> 1/rowsum
    inv_kernel<<<NB * NL / 256, 256>>>();

    // 4) out[b][c][l] = (V . E) * inv[l]  (K = 2048)
    out_gemm<<<dim3(NL / BN, NC / BM, NB), NTHREADS, SMEM_BYTES>>>(out);
}

// round 16
// speedup vs baseline: 1.1591x; 1.0187x over previous
#include <cuda_runtime.h>
#include <cuda_fp16.h>
#include <cstdint>
#include <math.h>

#define NB 8
#define NC 256
#define NL 2048
#define BM 128
#define BN 256
#define BK 64                      // halves per chunk (128 bytes per row)
#define NTHREADS 256
#define NST 4
#define L2E 1.4426950408889634f

// stage: A 128 rows x 128B (16KB) + B 256 rows x 128B (32KB) = 48KB
#define ABYTES (128 * 128)
#define STB (48 * 1024)
#define SMEM_BYTES (NST * STB)            // 196608
#define SMEM_BYTES_OUT (SMEM_BYTES + 1024) // + inv region

// ---------------- scratch ----------------
__device__ __half g_xh[NL * NL];          // fp16 x
__device__ __half g_Wh[3 * NL * NL];      // fp16 Wq|Wk|Wv
__device__ __half g_Qt[NB * NL * NC];     // [b][l][c] scaled
__device__ __half g_Kt[NB * NL * NC];     // [b][m][c]
__device__ __half g_V [NB * NC * NL];     // [b][c][m]
__device__ __half g_S [NB * NL * NL];     // E = exp(score), unnormalized (fp16)
__device__ float  g_part[NB * NL * 8];    // per-(row, m-tile CTA) partial sums

// ---------------- helpers ----------------
__device__ __forceinline__ uint32_t smem_u32(const void* p) {
    uint32_t a;
    asm("{ .reg .u64 t; cvta.to.shared.u64 t, %1; cvt.u32.u64 %0, t; }"
        : "=r"(a) : "l"(p));
    return a;
}
__device__ __forceinline__ float ex2(float x) {
    float r;
    asm("ex2.approx.f32 %0, %1;" : "=f"(r) : "f"(x));
    return r;
}
__device__ __forceinline__ void cp_async16(uint32_t dst, const void* src) {
    asm volatile("cp.async.cg.shared.global [%0], [%1], 16;" :: "r"(dst), "l"(src));
}
__device__ __forceinline__ void ldsm4(uint32_t& r0, uint32_t& r1, uint32_t& r2,
                                      uint32_t& r3, uint32_t addr) {
    asm volatile("ldmatrix.sync.aligned.m8n8.x4.shared.b16 {%0,%1,%2,%3}, [%4];"
                 : "=r"(r0), "=r"(r1), "=r"(r2), "=r"(r3) : "r"(addr));
}
__device__ __forceinline__ void mma_f16(float& d0, float& d1, float& d2, float& d3,
                                        uint32_t a0, uint32_t a1, uint32_t a2, uint32_t a3,
                                        uint32_t b0, uint32_t b1) {
    asm volatile(
        "mma.sync.aligned.m16n8k16.row.col.f32.f16.f16.f32 "
        "{%0,%1,%2,%3}, {%4,%5,%6,%7}, {%8,%9}, {%0,%1,%2,%3};"
        : "+f"(d0), "+f"(d1), "+f"(d2), "+f"(d3)
        : "r"(a0), "r"(a1), "r"(a2), "r"(a3), "r"(b0), "r"(b1));
}

// ===========================================================================
// fp16 mainloop: CTA 128x256, warp 64x64 (2x4 grid), XOR-swizzled smem,
// NST-stage cp.async, fragment double-buffering. acc[4][8][4] fp32.
// ===========================================================================
__device__ __forceinline__ void mainloop_h(
    const __half* __restrict__ A, const __half* __restrict__ B,
    int K, int ldA, int ldB, int r0, int c0,
    int tid, int wm, int wn, int lane,
    float acc[4][8][4])
{
    extern __shared__ float smem[];
    const uint32_t sbase = smem_u32(smem);
    const int nch = K / BK;

    const int lrow = tid >> 3;                       // 0..31
    const uint32_t lcb = (uint32_t)((tid & 7) * 16); // byte col within 128B row

    uint32_t qa[4], qb[4];
    {
        const int ar = wm + (lane & 15);
        const uint32_t ac = (uint32_t)(((lane >> 4) & 1) * 16);
#pragma unroll
        for (int mt = 0; mt < 4; mt++) {
            const int r = ar + mt * 16;
            qa[mt] = (uint32_t)(r * 128) + (ac ^ (((uint32_t)r & 7u) << 4));
        }
        const int br = wn + ((lane >> 3) & 1) * 8 + (lane & 7);
        const uint32_t bc = (uint32_t)(((lane >> 4) & 1) * 16);
#pragma unroll
        for (int ntp = 0; ntp < 4; ntp++) {
            const int r = br + ntp * 16;
            qb[ntp] = (uint32_t)(r * 128) + (bc ^ (((uint32_t)r & 7u) << 4));
        }
    }

    auto load_chunk = [&](int i) {
        const int s = i % NST;
        const uint32_t dA = sbase + (uint32_t)(s * STB);
        const uint32_t dB = dA + (uint32_t)ABYTES;
        const __half* Ab = A + (size_t)r0 * ldA + (size_t)i * BK + (tid & 7) * 8;
        const __half* Bb = B + (size_t)c0 * ldB + (size_t)i * BK + (tid & 7) * 8;
#pragma unroll
        for (int p = 0; p < 4; p++) {
            const int row = lrow + p * 32;
            const uint32_t off = (uint32_t)(row * 128) + (lcb ^ (((uint32_t)row & 7u) << 4));
            cp_async16(dA + off, Ab + (size_t)row * ldA);
        }
#pragma unroll
        for (int p = 0; p < 8; p++) {
            const int row = lrow + p * 32;
            const uint32_t off = (uint32_t)(row * 128) + (lcb ^ (((uint32_t)row & 7u) << 4));
            cp_async16(dB + off, Bb + (size_t)row * ldB);
        }
        asm volatile("cp.async.commit_group;");
    };

    // fragment double buffers
    uint32_t a[2][4][4], b[2][4][4];

    auto load_frags = [&](int buf, uint32_t sA, uint32_t sB, int s16) {
        const uint32_t kb = (uint32_t)(s16 * 32);
#pragma unroll
        for (int mt = 0; mt < 4; mt++)
            ldsm4(a[buf][mt][0], a[buf][mt][1], a[buf][mt][2], a[buf][mt][3],
                  (sA + qa[mt]) ^ kb);
#pragma unroll
        for (int ntp = 0; ntp < 4; ntp++)
            ldsm4(b[buf][ntp][0], b[buf][ntp][1], b[buf][ntp][2], b[buf][ntp][3],
                  (sB + qb[ntp]) ^ kb);
    };

    auto mma_all = [&](int buf) {
#pragma unroll
        for (int mt = 0; mt < 4; mt++)
#pragma unroll
            for (int nt = 0; nt < 8; nt++)
                mma_f16(acc[mt][nt][0], acc[mt][nt][1], acc[mt][nt][2], acc[mt][nt][3],
                        a[buf][mt][0], a[buf][mt][1], a[buf][mt][2], a[buf][mt][3],
                        b[buf][nt >> 1][nt & 1], b[buf][nt >> 1][(nt & 1) + 2]);
    };

    // prologue: NST-1 chunks in flight, then first frag load
#pragma unroll
    for (int i = 0; i < NST - 1; i++) load_chunk(i);
    asm volatile("cp.async.wait_group %0;" :: "n"(NST - 2));
    __syncthreads();
    load_frags(0, sbase, sbase + (uint32_t)ABYTES, 0);

    for (int j = 0; j < nch; j++) {
        const uint32_t sA = sbase + (uint32_t)((j % NST) * STB);
        const uint32_t sB = sA + (uint32_t)ABYTES;
        if (j + NST - 1 < nch) load_chunk(j + NST - 1);

#pragma unroll
        for (int s16 = 0; s16 < 4; s16++) {
            const int cur = s16 & 1, nxt = cur ^ 1;
            if (s16 < 3) {
                load_frags(nxt, sA, sB, s16 + 1);
                mma_all(cur);
            } else {
                mma_all(cur);        // consume last frags before barrier
                if (j + 1 < nch) {
                    asm volatile("cp.async.wait_group %0;" :: "n"(NST - 2));
                    __syncthreads();
                    const uint32_t nA = sbase + (uint32_t)(((j + 1) % NST) * STB);
                    load_frags(nxt, nA, nA + (uint32_t)ABYTES, 0);
                }
            }
        }
    }
}

// ---------------------------------------------------------------------------
// Merged fp32 -> fp16 conversion, 16 floats per thread (MLP 4).
// ---------------------------------------------------------------------------
__global__ void f2h_all(const float* __restrict__ x,  const float* __restrict__ Wq,
                        const float* __restrict__ Wk, const float* __restrict__ Wv)
{
    const int which = blockIdx.y;
    const float* src = (which == 0) ? x : (which == 1) ? Wq : (which == 2) ? Wk : Wv;
    __half* dst = (which == 0) ? g_xh : g_Wh + (size_t)(which - 1) * NL * NL;

    const int i = blockIdx.x * blockDim.x + threadIdx.x;   // 16 floats each
    float4 a = ((const float4*)src)[4 * i];
    float4 b = ((const float4*)src)[4 * i + 1];
    float4 c = ((const float4*)src)[4 * i + 2];
    float4 d = ((const float4*)src)[4 * i + 3];

    __half2 h0 = __floats2half2_rn(a.x, a.y);
    __half2 h1 = __floats2half2_rn(a.z, a.w);
    __half2 h2 = __floats2half2_rn(b.x, b.y);
    __half2 h3 = __floats2half2_rn(b.z, b.w);
    __half2 h4 = __floats2half2_rn(c.x, c.y);
    __half2 h5 = __floats2half2_rn(c.z, c.w);
    __half2 h6 = __floats2half2_rn(d.x, d.y);
    __half2 h7 = __floats2half2_rn(d.z, d.w);

    uint4 o0, o1;
    o0.x = *(uint32_t*)&h0; o0.y = *(uint32_t*)&h1;
    o0.z = *(uint32_t*)&h2; o0.w = *(uint32_t*)&h3;
    o1.x = *(uint32_t*)&h4; o1.y = *(uint32_t*)&h5;
    o1.z = *(uint32_t*)&h6; o1.w = *(uint32_t*)&h7;
    ((uint4*)dst)[2 * i]     = o0;
    ((uint4*)dst)[2 * i + 1] = o1;
}

// ---------------------------------------------------------------------------
// Merged QKV projection GEMM. cols 0..2047 -> Q (transposed+scaled),
// 2048..4095 -> K (transposed), 4096..6143 -> V (plain).
// Q/K transposed stores are smem-staged for full coalescing.
// ---------------------------------------------------------------------------
__global__ __launch_bounds__(NTHREADS)
void qkv_gemm(const float* __restrict__ bq, const float* __restrict__ bk,
              const float* __restrict__ bv)
{
    extern __shared__ float smem[];

    const int tid = threadIdx.x;
    const int wid = tid >> 5;
    const int lane = tid & 31;
    const int g = lane >> 2;
    const int t = lane & 3;
    const int wm = (wid & 1) * 64;
    const int wn = (wid >> 1) * 64;

    const int r0 = blockIdx.y * BM;
    const int gc0 = blockIdx.x * BN;
    const int widx = gc0 >> 11;
    const int c0 = gc0 & (NL - 1);

    const __half* W   = g_Wh + (size_t)widx * NL * NL;
    const float* bias = (widx == 0) ? bq : (widx == 1) ? bk : bv;
    const float scale = (widx == 0) ? 0.022097086912079612f : 1.0f;

    float acc[4][8][4];
#pragma unroll
    for (int i = 0; i < 4; i++)
#pragma unroll
        for (int j = 0; j < 8; j++)
#pragma unroll
            for (int k = 0; k < 4; k++) acc[i][j][k] = 0.0f;

    mainloop_h(g_xh, W, NL, NL, NL, r0, c0, tid, wm, wn, lane, acc);

    const int bb  = r0 >> 8;
    const int cl0 = r0 & (NC - 1);

    if (widx < 2) {
        // stage 256(l) x 128(c) fp16 tile in smem, then coalesced stores
        __syncthreads();                 // all warps done with pipeline smem
        __half* st = (__half*)smem;      // row stride 136 halves (17 uint4)
#pragma unroll
        for (int mt = 0; mt < 4; mt++) {
            const int cA = wm + mt * 16 + g;   // local c
#pragma unroll
            for (int nt = 0; nt < 8; nt++) {
                const int ll = wn + nt * 8 + 2 * t;   // local l
                const float b0 = bias[c0 + ll], b1 = bias[c0 + ll + 1];
                st[ll * 136 + cA]           = __float2half_rn((acc[mt][nt][0] + b0) * scale);
                st[(ll + 1) * 136 + cA]     = __float2half_rn((acc[mt][nt][1] + b1) * scale);
                st[ll * 136 + cA + 8]       = __float2half_rn((acc[mt][nt][2] + b0) * scale);
                st[(ll + 1) * 136 + cA + 8] = __float2half_rn((acc[mt][nt][3] + b1) * scale);
            }
        }
        __syncthreads();
        __half* Tb = ((widx == 0) ? g_Qt : g_Kt) + (size_t)bb * NL * NC;
#pragma unroll
        for (int p = 0; p < 16; p++) {
            const int idx = tid + p * 256;       // 0..4095 uint4s
            const int ll = idx >> 4;             // 0..255
            const int cc = (idx & 15) * 8;       // 0..120 halves
            uint4 v = *(const uint4*)&st[ll * 136 + cc];
            *(uint4*)&Tb[(size_t)(c0 + ll) * NC + cl0 + cc] = v;
        }
    } else {
#pragma unroll
        for (int mt = 0; mt < 4; mt++) {
            const int row = r0 + wm + mt * 16 + g;
#pragma unroll
            for (int nt = 0; nt < 8; nt++) {
                const int col = c0 + wn + nt * 8 + 2 * t;
                const float b0 = bias[col], b1 = bias[col + 1];
                __half2 lo = __floats2half2_rn(acc[mt][nt][0] + b0, acc[mt][nt][1] + b1);
                __half2 hi = __floats2half2_rn(acc[mt][nt][2] + b0, acc[mt][nt][3] + b1);
                *(__half2*)&g_V[(size_t)row * NL + col]       = lo;
                *(__half2*)&g_V[(size_t)(row + 8) * NL + col] = hi;
            }
        }
    }
}

// ---------------------------------------------------------------------------
// Score GEMM: E[b][l][m] = exp(Qt[b][l][:] . Kt[b][m][:])  (K=256, fp16 E)
// Epilogue also emits per-CTA partial row sums of E (fp32) to g_part.
// ---------------------------------------------------------------------------
__global__ __launch_bounds__(NTHREADS)
void score_gemm()
{
    extern __shared__ float smem[];

    const int tid = threadIdx.x;
    const int wid = tid >> 5;
    const int lane = tid & 31;
    const int g = lane >> 2;
    const int t = lane & 3;
    const int wm = (wid & 1) * 64;
    const int wn = (wid >> 1) * 64;
    const int wcol = wid >> 1;        // 0..3 (warp column index)

    const int z = blockIdx.z;
    const __half* A = g_Qt + (size_t)z * NL * NC;
    const __half* B = g_Kt + (size_t)z * NL * NC;
    const int r0 = blockIdx.y * BM;
    const int c0 = blockIdx.x * BN;

    float acc[4][8][4];
#pragma unroll
    for (int i = 0; i < 4; i++)
#pragma unroll
        for (int j = 0; j < 8; j++)
#pragma unroll
            for (int k = 0; k < 4; k++) acc[i][j][k] = 0.0f;

    mainloop_h(A, B, NC, NC, NC, r0, c0, tid, wm, wn, lane, acc);

    __half* Cb = g_S + (size_t)z * NL * NL;
    float rsum[4][2];                 // per mt: row, row+8 partial col-sums
#pragma unroll
    for (int mt = 0; mt < 4; mt++) { rsum[mt][0] = 0.0f; rsum[mt][1] = 0.0f; }

#pragma unroll
    for (int mt = 0; mt < 4; mt++) {
        const int row = r0 + wm + mt * 16 + g;
#pragma unroll
        for (int nt = 0; nt < 8; nt++) {
            const int col = c0 + wn + nt * 8 + 2 * t;
            float e0 = ex2(acc[mt][nt][0] * L2E);
            float e1 = ex2(acc[mt][nt][1] * L2E);
            float e2 = ex2(acc[mt][nt][2] * L2E);
            float e3 = ex2(acc[mt][nt][3] * L2E);
            rsum[mt][0] += e0 + e1;
            rsum[mt][1] += e2 + e3;
            *(__half2*)&Cb[(size_t)row * NL + col]       = __floats2half2_rn(e0, e1);
            *(__half2*)&Cb[(size_t)(row + 8) * NL + col] = __floats2half2_rn(e2, e3);
        }
    }

    // reduce over t within each quad (lanes 4g+t): xor 1, xor 2
#pragma unroll
    for (int mt = 0; mt < 4; mt++)
#pragma unroll
        for (int h = 0; h < 2; h++) {
            rsum[mt][h] += __shfl_xor_sync(0xFFFFFFFFu, rsum[mt][h], 1);
            rsum[mt][h] += __shfl_xor_sync(0xFFFFFFFFu, rsum[mt][h], 2);
        }

    // cross-warp-column combine via smem [128 rows][4 warp cols]
    float* sred = smem;
    __syncthreads();
    if (t == 0) {
#pragma unroll
        for (int mt = 0; mt < 4; mt++) {
            const int rl = wm + mt * 16 + g;
            sred[rl * 4 + wcol]       = rsum[mt][0];
            sred[(rl + 8) * 4 + wcol] = rsum[mt][1];
        }
    }
    __syncthreads();
    if (tid < 128) {
        const float s4 = sred[tid * 4 + 0] + sred[tid * 4 + 1]
                       + sred[tid * 4 + 2] + sred[tid * 4 + 3];
        g_part[((size_t)z * NL + r0 + tid) * 8 + blockIdx.x] = s4;
    }
}

// ---------------------------------------------------------------------------
// Output GEMM: out[b][c][l] = (V[b][c][:] . E[b][l][:]) / rowsum(E)[l]
// Inverse row sums computed cooperatively in the PROLOGUE into smem
// (region beyond the pipeline stages), read back in the epilogue.
// ---------------------------------------------------------------------------
__global__ __launch_bounds__(NTHREADS)
void out_gemm(float* __restrict__ out)
{
    extern __shared__ float smem[];
    float* sinv = smem + NST * STB / 4;   // 256 floats

    const int tid = threadIdx.x;
    const int wid = tid >> 5;
    const int lane = tid & 31;
    const int g = lane >> 2;
    const int t = lane & 3;
    const int wm = (wid & 1) * 64;
    const int wn = (wid >> 1) * 64;

    const int z = blockIdx.z;
    const __half* A = g_V + (size_t)z * NC * NL;
    const __half* B = g_S + (size_t)z * NL * NL;
    const int r0 = blockIdx.y * BM;
    const int c0 = blockIdx.x * BN;

    // prologue: each thread computes 1/rowsum for row (c0 + tid)
    {
        const float* pp = g_part + ((size_t)z * NL + c0 + tid) * 8;
        float4 a4 = *(const float4*)pp;
        float4 b4 = *(const float4*)(pp + 4);
        const float tot = (a4.x + a4.y) + (a4.z + a4.w)
                        + (b4.x + b4.y) + (b4.z + b4.w);
        sinv[tid] = 1.0f / tot;
        // ordering vs epilogue reads is guaranteed by mainloop's __syncthreads
    }

    float acc[4][8][4];
#pragma unroll
    for (int i = 0; i < 4; i++)
#pragma unroll
        for (int j = 0; j < 8; j++)
#pragma unroll
            for (int k = 0; k < 4; k++) acc[i][j][k] = 0.0f;

    mainloop_h(A, B, NL, NL, NL, r0, c0, tid, wm, wn, lane, acc);

    float iv[8][2];
#pragma unroll
    for (int nt = 0; nt < 8; nt++) {
        const int cl = wn + nt * 8 + 2 * t;
        iv[nt][0] = sinv[cl];
        iv[nt][1] = sinv[cl + 1];
    }

    float* Cb = out + (size_t)z * NC * NL;
#pragma unroll
    for (int mt = 0; mt < 4; mt++) {
        const int row = r0 + wm + mt * 16 + g;
#pragma unroll
        for (int nt = 0; nt < 8; nt++) {
            const int col = c0 + wn + nt * 8 + 2 * t;
            *(float2*)&Cb[(size_t)row * NL + col] =
                make_float2(acc[mt][nt][0] * iv[nt][0], acc[mt][nt][1] * iv[nt][1]);
            *(float2*)&Cb[(size_t)(row + 8) * NL + col] =
                make_float2(acc[mt][nt][2] * iv[nt][0], acc[mt][nt][3] * iv[nt][1]);
        }
    }
}

// ---------------------------------------------------------------------------
extern "C" void kernel_launch(void* const* d_in, const int* in_sizes, int n_in,
                              void* d_out, int out_size)
{
    const float* x  = (const float*)d_in[0];
    const float* Wq = (const float*)d_in[1];
    const float* bq = (const float*)d_in[2];
    const float* Wk = (const float*)d_in[3];
    const float* bk = (const float*)d_in[4];
    const float* Wv = (const float*)d_in[5];
    const float* bv = (const float*)d_in[6];
    float* out = (float*)d_out;

    cudaFuncSetAttribute((const void*)qkv_gemm,   cudaFuncAttributeMaxDynamicSharedMemorySize, SMEM_BYTES);
    cudaFuncSetAttribute((const void*)score_gemm, cudaFuncAttributeMaxDynamicSharedMemorySize, SMEM_BYTES);
    cudaFuncSetAttribute((const void*)out_gemm,   cudaFuncAttributeMaxDynamicSharedMemorySize, SMEM_BYTES_OUT);

    // 0) fp32 -> fp16 conversion (one launch, 16 floats/thread)
    f2h_all<<<dim3(NL * NL / 16 / 256, 4), 256>>>(x, Wq, Wk, Wv);

    // 1) fused QKV projections (N = 6144)
    qkv_gemm<<<dim3(3 * NL / BN, (NB * NC) / BM, 1), NTHREADS, SMEM_BYTES>>>(bq, bk, bv);

    // 2) E = exp(scaled scores), fp16 + per-CTA row partial sums (K = 256)
    score_gemm<<<dim3(NL / BN, NL / BM, NB), NTHREADS, SMEM_BYTES>>>();

    // 3) out[b][c][l] = (V . E) * inv[l]  (K = 2048, inv in prologue)
    out_gemm<<<dim3(NL / BN, NC / BM, NB), NTHREADS, SMEM_BYTES_OUT>>>(out);
}